// round 17
// baseline (speedup 1.0000x reference)
#include <cuda_runtime.h>
#include <cuda_fp16.h>
#include <cstdint>

// Problem constants (B=2, S=4096, D=2048, E=8, DFF=8192, TOP_K=2)
#define NTOK   8192
#define DMODEL 2048
#define NEXP   8
#define FFDIM  8192
#define TOPK   2

// ---------------- device scratch (allocation-free rule: __device__ globals) --
__device__ float  g_logits[NTOK * NEXP];
__device__ int    g_sel[TOPK];
__device__ __half g_xh[(size_t)NTOK * DMODEL];        // x  fp16 [M,K]
__device__ __half g_h0[(size_t)NTOK * FFDIM];         // h expert0 fp16 [M,K]
__device__ __half g_h1[(size_t)NTOK * FFDIM];         // h expert1 fp16 [M,K]
__device__ __half g_w1t[2][(size_t)FFDIM * DMODEL];   // w1^T fp16 [N=FF, K=D]
__device__ __half g_w2t[2][(size_t)DMODEL * FFDIM];   // w2^T fp16 [N=D,  K=FF]

// ---------------- helpers ----------------------------------------------------
__device__ __forceinline__ void cp16(void* smem, const void* gmem) {
    uint32_t s = (uint32_t)__cvta_generic_to_shared(smem);
    asm volatile("cp.async.cg.shared.global [%0], [%1], 16;\n" :: "r"(s), "l"(gmem));
}
__device__ __forceinline__ void cp_commit() {
    asm volatile("cp.async.commit_group;\n" ::: "memory");
}
template <int N>
__device__ __forceinline__ void cp_wait() {
    asm volatile("cp.async.wait_group %0;\n" :: "n"(N) : "memory");
}
__device__ __forceinline__ void ldsm4(uint32_t* r, uint32_t addr) {
    asm volatile("ldmatrix.sync.aligned.m8n8.x4.shared.b16 {%0,%1,%2,%3}, [%4];"
                 : "=r"(r[0]), "=r"(r[1]), "=r"(r[2]), "=r"(r[3]) : "r"(addr));
}
__device__ __forceinline__ float tanh_fast(float x) {
    float y;
    asm("tanh.approx.f32 %0, %1;" : "=f"(y) : "f"(x));
    return y;
}

// ---------------- fused router + x->fp16 convert -----------------------------
__global__ void router_cvt_kernel(const float* __restrict__ x,
                                  const float* __restrict__ gw,
                                  __half* __restrict__ xh) {
    int n = blockIdx.x;
    const float* xr = x + (size_t)n * DMODEL;
    __half* xo = xh + (size_t)n * DMODEL;
    int base = threadIdx.x * 8;            // 256 threads x 8 elems = 2048

    float4 v0 = *reinterpret_cast<const float4*>(xr + base);
    float4 v1 = *reinterpret_cast<const float4*>(xr + base + 4);
    __half2* out2 = reinterpret_cast<__half2*>(xo + base);
    out2[0] = __floats2half2_rn(v0.x, v0.y);
    out2[1] = __floats2half2_rn(v0.z, v0.w);
    out2[2] = __floats2half2_rn(v1.x, v1.y);
    out2[3] = __floats2half2_rn(v1.z, v1.w);

    float acc[NEXP];
#pragma unroll
    for (int e = 0; e < NEXP; e++) {
        const float* gr = gw + e * DMODEL + base;
        float s = v0.x * gr[0] + v0.y * gr[1] + v0.z * gr[2] + v0.w * gr[3]
                + v1.x * gr[4] + v1.y * gr[5] + v1.z * gr[6] + v1.w * gr[7];
        acc[e] = s;
    }
#pragma unroll
    for (int e = 0; e < NEXP; e++)
#pragma unroll
        for (int off = 16; off; off >>= 1)
            acc[e] += __shfl_xor_sync(0xffffffffu, acc[e], off);

    __shared__ float red[NEXP][8];
    int w = threadIdx.x >> 5, lane = threadIdx.x & 31;
    if (lane == 0) {
#pragma unroll
        for (int e = 0; e < NEXP; e++) red[e][w] = acc[e];
    }
    __syncthreads();
    if (threadIdx.x < NEXP) {
        float s = 0.f;
#pragma unroll
        for (int ww = 0; ww < 8; ww++) s += red[threadIdx.x][ww];
        g_logits[n * NEXP + threadIdx.x] = s;
    }
}

// fused: per-expert logit sums over all tokens + top-2 selection, one block
__global__ void sumtopk_kernel() {
    float acc[NEXP];
#pragma unroll
    for (int e = 0; e < NEXP; e++) acc[e] = 0.f;
    for (int n = threadIdx.x; n < NTOK; n += 256) {
        const float* lr = g_logits + n * NEXP;
#pragma unroll
        for (int e = 0; e < NEXP; e++) acc[e] += lr[e];
    }
#pragma unroll
    for (int e = 0; e < NEXP; e++)
#pragma unroll
        for (int off = 16; off; off >>= 1)
            acc[e] += __shfl_xor_sync(0xffffffffu, acc[e], off);

    __shared__ float red[NEXP][8];
    int w = threadIdx.x >> 5, lane = threadIdx.x & 31;
    if (lane == 0) {
#pragma unroll
        for (int e = 0; e < NEXP; e++) red[e][w] = acc[e];
    }
    __syncthreads();
    if (threadIdx.x == 0) {
        float sums[NEXP];
#pragma unroll
        for (int e = 0; e < NEXP; e++) {
            float s = 0.f;
#pragma unroll
            for (int ww = 0; ww < 8; ww++) s += red[e][ww];
            sums[e] = s;
        }
        int b = 0;
        for (int i = 1; i < NEXP; i++)
            if (sums[i] > sums[b]) b = i;         // strict > : lower idx on tie
        int s = (b == 0) ? 1 : 0;
        for (int i = 0; i < NEXP; i++)
            if (i != b && sums[i] > sums[s]) s = i;
        g_sel[0] = b;
        g_sel[1] = s;
    }
}

// zero-init the fp32 output (atomic accumulation target)
__global__ void zero_out_kernel(float4* __restrict__ dst, size_t n4) {
    size_t i = (size_t)blockIdx.x * blockDim.x + threadIdx.x;
    if (i < n4) dst[i] = make_float4(0.f, 0.f, 0.f, 0.f);
}

// All 4 weight transposes in one launch. 64x64 tiles: fp16 writes are 128B/row.
// z: 0,1 -> w1 expert z;  2,3 -> w2 expert z-2.
__global__ void transpose_all_kernel(const float* __restrict__ w1,
                                     const float* __restrict__ w2,
                                     __half* __restrict__ w1t0, __half* __restrict__ w1t1,
                                     __half* __restrict__ w2t0, __half* __restrict__ w2t1) {
    __shared__ float t[64][65];
    const int z = blockIdx.z;
    const bool is1 = (z < 2);
    const int K = is1 ? DMODEL : FFDIM;
    const int N = is1 ? FFDIM : DMODEL;
    const int e = g_sel[z & 1];
    const float* src = (is1 ? w1 : w2) + (size_t)e * K * N;
    __half* dst = is1 ? (z == 0 ? w1t0 : w1t1) : (z == 2 ? w2t0 : w2t1);

    const int tilesN = N >> 6;
    const int tn = blockIdx.x % tilesN, tk = blockIdx.x / tilesN;
    const int n0 = tn * 64, k0 = tk * 64;
    const int tx = threadIdx.x;            // 0..63
    const int ty = threadIdx.y;            // 0..3

#pragma unroll
    for (int i = ty; i < 64; i += 4)
        t[i][tx] = src[(size_t)(k0 + i) * N + n0 + tx];
    __syncthreads();
#pragma unroll
    for (int i = ty; i < 64; i += 4)
        dst[(size_t)(n0 + i) * K + k0 + tx] = __float2half_rn(t[tx][i]);
}

// ---------------- fp16 GEMM: 128x256 CTA, 64x64 warp, ldmatrix + cp.async ----
#define BM 128
#define BN 256
#define BK 32
#define ASTRH 40    // halves per row (BK+8): 80B stride; 16B-aligned, ldsm conflict-free
#define BSTRH 40
#define NSTAGE 4
#define A_TILE_H (BM * ASTRH)              // halves
#define B_TILE_H (BN * BSTRH)
#define SMEM_BYTES (NSTAGE * (A_TILE_H + B_TILE_H) * 2)

__device__ __forceinline__ void mma_f16(float* c, const uint32_t* a, const uint32_t* b) {
    asm volatile(
        "mma.sync.aligned.m16n8k16.row.col.f32.f16.f16.f32 "
        "{%0,%1,%2,%3}, {%4,%5,%6,%7}, {%8,%9}, {%0,%1,%2,%3};\n"
        : "+f"(c[0]), "+f"(c[1]), "+f"(c[2]), "+f"(c[3])
        : "r"(a[0]), "r"(a[1]), "r"(a[2]), "r"(a[3]), "r"(b[0]), "r"(b[1]));
}

__device__ __forceinline__ float gelu_tanh(float x) {
    float x3 = x * x * x;
    float t  = tanh_fast(0.7978845608028654f * (x + 0.044715f * x3));
    return 0.5f * x * (1.0f + t);
}

// Shared mainloop: computes acc for one (m0,n0,K-range) tile.
struct GemmCore {
    float acc[4][8][4];
    int r0_[4];
    int cc_[8];

    __device__ __forceinline__ void run(const __half* __restrict__ A,
                                        const __half* __restrict__ Bt,
                                        int m0, int n0, int K, int kstart, int klen) {
        extern __shared__ __half smh[];
        __half* As = smh;
        __half* Bs = smh + NSTAGE * A_TILE_H;

        const int tid  = threadIdx.x;
        const int lane = tid & 31;
        const int wid  = tid >> 5;
        const int wm   = wid & 1;
        const int wn   = wid >> 1;
        const int g    = lane >> 2;
        const int tg   = lane & 3;

        const int lr  = lane & 7;
        const int sel = lane >> 3;
        uint32_t aoff[4], boff[4];
#pragma unroll
        for (int mt = 0; mt < 4; mt++) {
            int row = wm * 64 + mt * 16 + (sel & 1) * 8 + lr;
            aoff[mt] = (uint32_t)(row * ASTRH + (sel >> 1) * 8) * 2;
        }
#pragma unroll
        for (int p = 0; p < 4; p++) {
            int nn = wn * 64 + p * 16 + (sel >> 1) * 8 + lr;
            boff[p] = (uint32_t)(nn * BSTRH + (sel & 1) * 8) * 2;
        }
        const uint32_t As_u = (uint32_t)__cvta_generic_to_shared(As);
        const uint32_t Bs_u = (uint32_t)__cvta_generic_to_shared(Bs);

#pragma unroll
        for (int i = 0; i < 4; i++)
#pragma unroll
            for (int j = 0; j < 8; j++)
#pragma unroll
                for (int r = 0; r < 4; r++) acc[i][j][r] = 0.f;

#pragma unroll
        for (int mt = 0; mt < 4; mt++) r0_[mt] = m0 + wm * 64 + mt * 16 + g;
#pragma unroll
        for (int nt = 0; nt < 8; nt++) cc_[nt] = n0 + wn * 64 + nt * 8 + tg * 2;

        const int KT = klen / BK;

        auto issue_stage = [&](int s, int kt) {
            const int k0 = kstart + kt * BK;
            __half* as = As + s * A_TILE_H;
            __half* bs = Bs + s * B_TILE_H;
#pragma unroll
            for (int i = 0; i < 2; i++) {
                int idx = tid + i * 256;
                int r = idx >> 2, ch = idx & 3;
                cp16(&as[r * ASTRH + ch * 8], A + (size_t)(m0 + r) * K + k0 + ch * 8);
            }
#pragma unroll
            for (int i = 0; i < 4; i++) {
                int idx = tid + i * 256;
                int r = idx >> 2, ch = idx & 3;
                cp16(&bs[r * BSTRH + ch * 8], Bt + (size_t)(n0 + r) * K + k0 + ch * 8);
            }
        };

        issue_stage(0, 0); cp_commit();
        if (KT > 1) issue_stage(1, 1);
        cp_commit();
        if (KT > 2) issue_stage(2, 2);
        cp_commit();

        for (int kt = 0; kt < KT; kt++) {
            cp_wait<2>();
            __syncthreads();

            if (kt + 3 < KT) issue_stage((kt + 3) & (NSTAGE - 1), kt + 3);
            cp_commit();

            const uint32_t a_base = As_u + (uint32_t)((kt & (NSTAGE - 1)) * A_TILE_H) * 2;
            const uint32_t b_base = Bs_u + (uint32_t)((kt & (NSTAGE - 1)) * B_TILE_H) * 2;

#pragma unroll
            for (int ks = 0; ks < 2; ks++) {
                const uint32_t ko = ks * 32;
                uint32_t af[4][4], bq[4][4];
#pragma unroll
                for (int mt = 0; mt < 4; mt++) ldsm4(af[mt], a_base + aoff[mt] + ko);
#pragma unroll
                for (int p = 0; p < 4; p++)  ldsm4(bq[p],  b_base + boff[p] + ko);
#pragma unroll
                for (int mt = 0; mt < 4; mt++)
#pragma unroll
                    for (int nt = 0; nt < 8; nt++)
                        mma_f16(acc[mt][nt], af[mt], &bq[nt >> 1][(nt & 1) * 2]);
            }
        }
    }
};

// GEMM1 combined: grid.z = expert; Ch = fp16(gelu(A@B^T + bias)), full K
__global__ void __launch_bounds__(256, 1)
moe_gemm1(const __half* __restrict__ A,
          const __half* __restrict__ W0, const __half* __restrict__ W1,
          const float* __restrict__ Ball,
          int N, int K,
          __half* __restrict__ C0, __half* __restrict__ C1) {
    const int kidx = blockIdx.z;
    const __half* Bt = kidx ? W1 : W0;
    __half* C = kidx ? C1 : C0;

    GemmCore core;
    core.run(A, Bt, blockIdx.y * BM, blockIdx.x * BN, K, 0, K);

    const int e = g_sel[kidx];
    const float* bias = Ball + (size_t)e * N;
#pragma unroll
    for (int mt = 0; mt < 4; mt++) {
        int r0 = core.r0_[mt];
#pragma unroll
        for (int nt = 0; nt < 8; nt++) {
            int cc = core.cc_[nt];
            const float* cr = core.acc[mt][nt];
            float b0 = bias[cc], b1v = bias[cc + 1];
            __half2* p0 = (__half2*)(C + (size_t)r0 * N + cc);
            __half2* p1 = (__half2*)(C + (size_t)(r0 + 8) * N + cc);
            *p0 = __floats2half2_rn(gelu_tanh(cr[0] + b0), gelu_tanh(cr[1] + b1v));
            *p1 = __floats2half2_rn(gelu_tanh(cr[2] + b0), gelu_tanh(cr[3] + b1v));
        }
    }
}

// per-row routing weight for expert kidx, computed from logits (softmax of 2)
__device__ __forceinline__ float rw_of_row(int row, int s0, int s1, int kidx) {
    float l0 = g_logits[row * NEXP + s0];
    float l1 = g_logits[row * NEXP + s1];
    float m  = fmaxf(l0, l1);
    float e0 = __expf(l0 - m), e1 = __expf(l1 - m);
    float inv = 1.0f / (e0 + e1);
    return (kidx == 0 ? e0 : e1) * inv;
}

// GEMM2 combined: grid.z encodes {expert(z>>1), khalf(z&1)}; atomic accumulate.
__global__ void __launch_bounds__(256, 1)
moe_gemm2(const __half* __restrict__ H0, const __half* __restrict__ H1,
          const __half* __restrict__ W0, const __half* __restrict__ W1,
          const float* __restrict__ Ball,
          int N, int K, int klen,
          float* __restrict__ C) {
    const int z = blockIdx.z;
    const int kidx = z >> 1;
    const int kstart = (z & 1) * klen;
    const __half* A  = kidx ? H1 : H0;
    const __half* Bt = kidx ? W1 : W0;

    GemmCore core;
    core.run(A, Bt, blockIdx.y * BM, blockIdx.x * BN, K, kstart, klen);

    const int s0 = g_sel[0], s1 = g_sel[1];
    const int e = kidx ? s1 : s0;
    const float* bias = Ball + (size_t)e * N;
    const bool addb = (kstart == 0);
#pragma unroll
    for (int mt = 0; mt < 4; mt++) {
        int r0 = core.r0_[mt];
        float w0 = rw_of_row(r0,     s0, s1, kidx);
        float w1 = rw_of_row(r0 + 8, s0, s1, kidx);
#pragma unroll
        for (int nt = 0; nt < 8; nt++) {
            int cc = core.cc_[nt];
            const float* cr = core.acc[mt][nt];
            float b0 = addb ? bias[cc] : 0.f;
            float b1v = addb ? bias[cc + 1] : 0.f;
            float* p0 = C + (size_t)r0 * N + cc;
            float* p1 = C + (size_t)(r0 + 8) * N + cc;
            atomicAdd(p0,     w0 * (cr[0] + b0));
            atomicAdd(p0 + 1, w0 * (cr[1] + b1v));
            atomicAdd(p1,     w1 * (cr[2] + b0));
            atomicAdd(p1 + 1, w1 * (cr[3] + b1v));
        }
    }
}

// ---------------- launch (strict serial, single stream) ----------------------
extern "C" void kernel_launch(void* const* d_in, const int* in_sizes, int n_in,
                              void* d_out, int out_size) {
    const float* x  = (const float*)d_in[0];   // [8192,2048]
    const float* gw = (const float*)d_in[1];   // [8,2048]
    const float* w1 = (const float*)d_in[2];   // [8,2048,8192]
    const float* b1 = (const float*)d_in[3];   // [8,8192]
    const float* w2 = (const float*)d_in[4];   // [8,8192,2048]
    const float* b2 = (const float*)d_in[5];   // [8,2048]
    float* out = (float*)d_out;                // [8192,2048]

    __half *xh, *h0, *h1, *w1t0, *w2t0;
    cudaGetSymbolAddress((void**)&xh,   g_xh);
    cudaGetSymbolAddress((void**)&h0,   g_h0);
    cudaGetSymbolAddress((void**)&h1,   g_h1);
    cudaGetSymbolAddress((void**)&w1t0, g_w1t);
    cudaGetSymbolAddress((void**)&w2t0, g_w2t);
    __half* w1t1 = w1t0 + (size_t)FFDIM * DMODEL;
    __half* w2t1 = w2t0 + (size_t)DMODEL * FFDIM;

    cudaFuncSetAttribute(moe_gemm1, cudaFuncAttributeMaxDynamicSharedMemorySize, SMEM_BYTES);
    cudaFuncSetAttribute(moe_gemm2, cudaFuncAttributeMaxDynamicSharedMemorySize, SMEM_BYTES);

    // zero the atomic-accumulation output (independent of routing)
    size_t on4 = ((size_t)NTOK * DMODEL) >> 2;
    zero_out_kernel<<<(unsigned)((on4 + 255) / 256), 256>>>((float4*)out, on4);

    // routing (+x convert), then fused sum+top2
    router_cvt_kernel<<<NTOK, 256>>>(x, gw, xh);
    sumtopk_kernel<<<1, 256>>>();

    // all 4 weight transposes, one launch (4096 64x64 tiles per matrix)
    dim3 tb(64, 4);
    dim3 tgrid(4096, 1, 4);
    transpose_all_kernel<<<tgrid, tb>>>(w1, w2, w1t0, w1t1, w2t0, w2t1);

    dim3 blk(256);
    dim3 gg1(FFDIM / BN, NTOK / BM, 2);     // (32,64,2): both experts, one launch
    moe_gemm1<<<gg1, blk, SMEM_BYTES>>>(xh, w1t0, w1t1, b1, FFDIM, DMODEL, h0, h1);

    dim3 gg2(DMODEL / BN, NTOK / BM, 4);    // (8,64,4): both experts x 2 K-halves
    moe_gemm2<<<gg2, blk, SMEM_BYTES>>>(h0, h1, w2t0, w2t1, b2,
                                        DMODEL, FFDIM, FFDIM / 2, out);
}